// round 8
// baseline (speedup 1.0000x reference)
#include <cuda_runtime.h>
#include <math.h>

// features: (B=16, C=256, H=64, W=64) fp32 ; out: (B, H, W) fp32
//
// R7: float2 loads + 8-way channel split across warps.
// Pixels paired into float2 groups (32768 groups). Block = 256 threads =
// 8 octants x 32 groups -> 64 pixels/block, grid = 1024 (wave-balanced).
// Each thread reduces 32 channels for its 2 pixels; each warp-LDG reads
// 256B contiguous (2 full lines). Partials (s,ss per 2 px) combined via
// smem across the 8 octants; 64 threads finish + store coalesced.

#define C_DIM   256
#define HW      4096
#define NPIX    65536
#define TPB     256
#define GRP_PER_BLK 32          // float2 groups per block (64 pixels)
#define GRP_PER_IMG 2048        // HW/2

__global__ void __launch_bounds__(TPB)
fis_kernel(const float2* __restrict__ f2,
           const float* __restrict__ W1,   // (3,16)
           const float* __restrict__ b1,   // 16
           const float* __restrict__ W2,   // (16,1)
           const float* __restrict__ b2,   // 1
           float* __restrict__ out)
{
    __shared__ float sp[81];                 // [0:48) W1, [48:64) b1, [64:80) W2, [80] b2
    __shared__ float4 red[8][GRP_PER_BLK];   // (s0, s1, ss0, ss1) per octant x group

    int tid = threadIdx.x;
    if (tid < 81) {
        float v;
        if (tid < 48)      v = W1[tid];
        else if (tid < 64) v = b1[tid - 48];
        else if (tid < 80) v = W2[tid - 64];
        else               v = b2[0];
        sp[tid] = v;
    }
    __syncthreads();

    int o = tid >> 5;                        // channel octant [0,8)
    int g = tid & 31;                        // group within block
    int G = blockIdx.x * GRP_PER_BLK + g;    // global float2-group id

    int b    = G >> 11;                      // / GRP_PER_IMG
    int gimg = G & (GRP_PER_IMG - 1);

    const float2* __restrict__ src =
        f2 + (size_t)b * C_DIM * GRP_PER_IMG + (size_t)(o * 32) * GRP_PER_IMG + gimg;

    float s0 = 0.f, s1 = 0.f, ss0 = 0.f, ss1 = 0.f;
    #pragma unroll 8
    for (int c = 0; c < 32; ++c) {
        float2 v = __ldg(src + (size_t)c * GRP_PER_IMG);
        s0 += v.x;  s1 += v.y;
        ss0 = fmaf(v.x, v.x, ss0);
        ss1 = fmaf(v.y, v.y, ss1);
    }

    red[o][g] = make_float4(s0, s1, ss0, ss1);
    __syncthreads();

    if (tid < 64) {
        int gg = tid >> 1;                   // group
        int h  = tid & 1;                    // which pixel of the pair

        float sv = 0.f, ssv = 0.f;
        #pragma unroll
        for (int k = 0; k < 8; ++k) {
            float4 r = red[k][gg];
            sv  += h ? r.y : r.x;
            ssv += h ? r.w : r.z;
        }

        const float inv_c  = 1.0f / 256.0f;
        const float inv_c1 = 1.0f / 255.0f;
        float mag = sqrtf(ssv * inv_c);
        float var = (ssv - sv * sv * inv_c) * inv_c1;
        var = fmaxf(var, 0.0f);
        float sd  = sqrtf(var);

        float x0 = fminf(mag, 1.0f);
        float x1 = fminf(var, 1.0f);
        float x2 = fminf(sd,  1.0f);

        float acc = sp[80];
        #pragma unroll
        for (int oo = 0; oo < 16; ++oo) {
            float hh = sp[48 + oo];
            hh = fmaf(x0, sp[oo],      hh);
            hh = fmaf(x1, sp[16 + oo], hh);
            hh = fmaf(x2, sp[32 + oo], hh);
            hh = fmaxf(hh, 0.0f);
            acc = fmaf(hh, sp[64 + oo], acc);
        }
        out[blockIdx.x * 64 + tid] = 1.0f / (1.0f + __expf(-acc));
    }
}

extern "C" void kernel_launch(void* const* d_in, const int* in_sizes, int n_in,
                              void* d_out, int out_size)
{
    const float2* f2 = (const float2*)d_in[0];
    const float*  W1 = (const float*)d_in[1];
    const float*  b1 = (const float*)d_in[2];
    const float*  W2 = (const float*)d_in[3];
    const float*  b2 = (const float*)d_in[4];
    float* out = (float*)d_out;

    fis_kernel<<<NPIX / 64, TPB>>>(f2, W1, b1, W2, b2, out);
}